// round 7
// baseline (speedup 1.0000x reference)
#include <cuda_runtime.h>

#define B 256
#define S 512
#define T 128
#define STARTT 125
#define STOPT 126
#define TB_PITCH 132  // padded row pitch (floats) for smem transT

// 64MB part-history scratch: hist[b][s][t]
__device__ float g_hist[(size_t)B * S * T];

// ---------------------------------------------------------------------------
// Kernel 1: forward Viterbi max-plus recurrence. One block per batch.
// Thread j holds trans[:, j] packed as 64 f32x2 register pairs.
// (identical to the R4/R6 passing configuration)
// ---------------------------------------------------------------------------
__global__ __launch_bounds__(128, 2) void k_forward(
    const float* __restrict__ feats, const float* __restrict__ trans) {
    const int b = blockIdx.x;
    const int j = threadIdx.x;

    unsigned long long c2[T / 2];
#pragma unroll
    for (int q = 0; q < T / 2; q++) {
        float lo = trans[(2 * q) * T + j];
        float hi = trans[(2 * q + 1) * T + j];
        asm("mov.b64 %0, {%1, %2};" : "=l"(c2[q]) : "f"(lo), "f"(hi));
    }
    float cstart;
    {
        float dead;
        asm("mov.b64 {%0, %1}, %2;" : "=f"(dead), "=f"(cstart)
            : "l"(c2[STARTT / 2]));
        (void)dead;
    }

    __shared__ __align__(16) float part[2][T];

    const float* fb = feats + (size_t)b * S * T;
    float* hb = g_hist + (size_t)b * S * T;

    float p0 = fb[j] + cstart;
    part[0][j] = p0;
    hb[j] = p0;
    float e1 = fb[T + j];
    float e2 = fb[2 * T + j];
    __syncthreads();

    const unsigned sbase0 = (unsigned)__cvta_generic_to_shared(&part[0][0]);

#pragma unroll 1
    for (int s = 1; s < S; s++) {
        float ecur = e1;
        e1 = e2;
        if (s + 2 < S) e2 = fb[(s + 2) * T + j];

        const unsigned pbase =
            sbase0 + (((s - 1) & 1) ? (unsigned)(T * 4) : 0u);

        float m0, m1, m2, m3;
        asm volatile(
            "{\n\t"
            ".reg .b64 p0, p1, s0, s1;\n\t"
            "ld.shared.v2.b64 {p0, p1}, [%4];\n\t"
            "add.rn.f32x2 s0, p0, %5;\n\t"
            "add.rn.f32x2 s1, p1, %6;\n\t"
            "mov.b64 {%0, %1}, s0;\n\t"
            "mov.b64 {%2, %3}, s1;\n\t"
            "}"
            : "=f"(m0), "=f"(m1), "=f"(m2), "=f"(m3)
            : "r"(pbase), "l"(c2[0]), "l"(c2[1]));
#pragma unroll
        for (int q = 1; q < 32; q++) {
            asm volatile(
                "{\n\t"
                ".reg .b64 p0, p1, s0, s1;\n\t"
                ".reg .f32 a0, a1, a2, a3;\n\t"
                "ld.shared.v2.b64 {p0, p1}, [%4];\n\t"
                "add.rn.f32x2 s0, p0, %5;\n\t"
                "add.rn.f32x2 s1, p1, %6;\n\t"
                "mov.b64 {a0, a1}, s0;\n\t"
                "mov.b64 {a2, a3}, s1;\n\t"
                "max.f32 %0, %0, a0;\n\t"
                "max.f32 %1, %1, a1;\n\t"
                "max.f32 %2, %2, a2;\n\t"
                "max.f32 %3, %3, a3;\n\t"
                "}"
                : "+f"(m0), "+f"(m1), "+f"(m2), "+f"(m3)
                : "r"(pbase + 16u * q), "l"(c2[2 * q]), "l"(c2[2 * q + 1]));
        }
        float np = fmaxf(fmaxf(m0, m1), fmaxf(m2, m3)) + ecur;
        part[s & 1][j] = np;
        hb[s * T + j] = np;
        __syncthreads();
    }
}

// monotonic float -> u32 key (order preserving for finite floats)
__device__ __forceinline__ unsigned fkey(float f) {
    unsigned u = __float_as_uint(f);
    return u ^ ((unsigned)((int)u >> 31) | 0x80000000u);
}

// first-index argmax over the warp's 4-per-lane keys; returns index to all
__device__ __forceinline__ int warp_argmax4(unsigned k0, unsigned k1,
                                            unsigned k2, unsigned k3, int l) {
    unsigned ka = (k0 > k1) ? k0 : k1;
    unsigned kb = (k2 > k3) ? k2 : k3;
    unsigned lm = (ka > kb) ? ka : kb;
    unsigned g = __reduce_max_sync(0xffffffffu, lm);
    unsigned bm = (k0 == g ? 1u : 0u) | (k1 == g ? 2u : 0u) |
                  (k2 == g ? 4u : 0u) | (k3 == g ? 8u : 0u);
    unsigned idxc = bm ? (unsigned)(4 * l + (__ffs((int)bm) - 1))
                       : 0x40000000u;
    return (int)__reduce_min_sync(0xffffffffu, idxc);
}

// ---------------------------------------------------------------------------
// Kernel 2: per-WARP traceback. Grid 64 x 128 threads; warp w of block g
// traces batch 4g+w -> 256 concurrent chains in ONE wave, 4 chains/SM on
// 4 distinct SMSPs. transT in padded smem (per block). 3-deep register
// prefetch ring for hist/feats rows.
// ---------------------------------------------------------------------------
__global__ __launch_bounds__(128, 1) void k_traceback(
    const float* __restrict__ feats, const float* __restrict__ trans,
    const void* __restrict__ mask, float* __restrict__ out) {
    const int tid = threadIdx.x;
    const int wid = tid >> 5;
    const int l = tid & 31;
    const int b = blockIdx.x * 4 + wid;

    extern __shared__ float sT[];  // [T][TB_PITCH], sT[j][i] = trans[i][j]

    // cooperative transpose of trans into padded smem (one-time)
    for (int k = tid; k < T * T; k += 128) {
        int i = k >> 7;    // row of trans
        int jj = k & 127;  // col of trans
        sT[jj * TB_PITCH + i] = trans[k];
    }
    __syncthreads();

    // ---- per-warp length: lane l counts 16 consecutive mask entries ----
    const unsigned w0 = *(const unsigned*)mask;  // dtype signature
    int cnt = 0;
    if (w0 == 0x01010101u) {  // 1-byte bool: 16 bytes = one uint4
        const uint4* m16 = (const uint4*)((const unsigned char*)mask +
                                          (size_t)b * S + l * 16);
        uint4 v = *m16;
        cnt = __popc(v.x) + __popc(v.y) + __popc(v.z) + __popc(v.w);
    } else if (w0 == 0x3F800000u) {  // float32
        const float* mf = (const float*)mask + (size_t)b * S + l * 16;
#pragma unroll
        for (int t = 0; t < 16; t++) cnt += (mf[t] != 0.f);
    } else if (w0 == 0x3F803F80u || w0 == 0x3C003C00u) {  // bf16 / f16
        const unsigned short* mh =
            (const unsigned short*)mask + (size_t)b * S + l * 16;
#pragma unroll
        for (int t = 0; t < 16; t++) cnt += (mh[t] != 0);
    } else {  // int32 0/1
        const int* mi = (const int*)mask + (size_t)b * S + l * 16;
#pragma unroll
        for (int t = 0; t < 16; t++) cnt += (mi[t] != 0);
    }
    cnt = __reduce_add_sync(0xffffffffu, cnt);
    const int last_pos = cnt - 1;

    const float4* hist4 =
        reinterpret_cast<const float4*>(g_hist + (size_t)b * S * T);
    const float4* feats4 =
        reinterpret_cast<const float4*>(feats + (size_t)b * S * T);

    // ---- final pointer: argmax_i(hist[last_pos][i] + trans[i][STOP]) ----
    int pointer;
    {
        float4 h = hist4[last_pos * 32 + l];
        float4 tr =
            reinterpret_cast<const float4*>(sT + STOPT * TB_PITCH)[l];
        unsigned k0 = fkey(h.x + tr.x), k1 = fkey(h.y + tr.y);
        unsigned k2 = fkey(h.z + tr.z), k3 = fkey(h.w + tr.w);
        pointer = warp_argmax4(k0, k1, k2, k3, l);
    }

    float* ob = out + (size_t)b * S;

    // positions past the sequence: zeros (matches zeroed back_points rows)
    for (int s = last_pos + 1 + l; s < S - 1; s += 32) ob[s] = 0.0f;
    if (l == 0) {
        ob[S - 1] = (float)pointer;
        ob[last_pos] = (float)pointer;
    }

    int ptr = pointer;
    const int s0 = last_pos - 1;
    if (s0 < 0) return;

#define HROW(ss) hist4[(ss) * 32 + l]
#define EROW(ss) feats4[((ss) + 1) * 32 + l]
    int r1 = s0 - 1 > 0 ? s0 - 1 : 0;
    int r2 = s0 - 2 > 0 ? s0 - 2 : 0;
    float4 hb0 = HROW(s0), hb1 = HROW(r1), hb2 = HROW(r2);
    float4 eb0 = EROW(s0), eb1 = EROW(r1), eb2 = EROW(r2);

    for (int s = s0; s >= 0; --s) {
        float4 h = hb0, er = eb0;
        // shift ring; issue next prefetch immediately (ptr-independent)
        hb0 = hb1; hb1 = hb2;
        eb0 = eb1; eb1 = eb2;
        int sp = s - 3; if (sp < 0) sp = 0;
        hb2 = HROW(sp);
        eb2 = EROW(sp);

        // trans[:, ptr] chunk from padded smem (LDS.128, conflict-free)
        float4 tc =
            reinterpret_cast<const float4*>(sT + ptr * TB_PITCH)[l];

        // scalar e = feats[b][s+1][ptr] extracted from prefetched row
        int comp = ptr & 3, src = ptr >> 2;
        float cand = (comp == 0) ? er.x
                   : (comp == 1) ? er.y
                   : (comp == 2) ? er.z : er.w;
        float e = __shfl_sync(0xffffffffu, cand, src);

        // exact replication of reference: (part + trans) + e, argmax first-idx
        unsigned k0 = fkey((h.x + tc.x) + e);
        unsigned k1 = fkey((h.y + tc.y) + e);
        unsigned k2 = fkey((h.z + tc.z) + e);
        unsigned k3 = fkey((h.w + tc.w) + e);
        ptr = warp_argmax4(k0, k1, k2, k3, l);
        if (l == 0) ob[s] = (float)ptr;
    }
#undef HROW
#undef EROW
}

// ---------------------------------------------------------------------------
extern "C" void kernel_launch(void* const* d_in, const int* in_sizes, int n_in,
                              void* d_out, int out_size) {
    // Identify inputs by element count:
    //   feats 16777216, transitions 16384, mask 131072
    const float* feats = nullptr;
    const void* mask = nullptr;
    const float* trans = nullptr;
    for (int i = 0; i < n_in; i++) {
        int n = in_sizes[i];
        if (n == B * S * T) feats = (const float*)d_in[i];
        else if (n == T * T) trans = (const float*)d_in[i];
        else mask = d_in[i];
    }
    float* out = (float*)d_out;
    (void)out_size;

    const int smem_tb = T * TB_PITCH * sizeof(float);  // 67584 B
    cudaFuncSetAttribute(k_traceback,
                         cudaFuncAttributeMaxDynamicSharedMemorySize, smem_tb);

    k_forward<<<B, T>>>(feats, trans);
    k_traceback<<<B / 4, T, smem_tb>>>(feats, trans, mask, out);
}

// round 8
// speedup vs baseline: 1.6207x; 1.6207x over previous
#include <cuda_runtime.h>
#include <cuda_pipeline_primitives.h>

#define B 256
#define S 512
#define T 128
#define STARTT 125
#define STOPT 126
#define TB_PITCH 132  // padded row pitch (floats) for smem transT

// 64MB part-history scratch: hist[b][s][t]
__device__ float g_hist[(size_t)B * S * T];

// ---------------------------------------------------------------------------
// Kernel 1: forward Viterbi max-plus recurrence. One block per batch.
// (identical to the R4/R6/R7 passing configuration)
// ---------------------------------------------------------------------------
__global__ __launch_bounds__(128, 2) void k_forward(
    const float* __restrict__ feats, const float* __restrict__ trans) {
    const int b = blockIdx.x;
    const int j = threadIdx.x;

    unsigned long long c2[T / 2];
#pragma unroll
    for (int q = 0; q < T / 2; q++) {
        float lo = trans[(2 * q) * T + j];
        float hi = trans[(2 * q + 1) * T + j];
        asm("mov.b64 %0, {%1, %2};" : "=l"(c2[q]) : "f"(lo), "f"(hi));
    }
    float cstart;
    {
        float dead;
        asm("mov.b64 {%0, %1}, %2;" : "=f"(dead), "=f"(cstart)
            : "l"(c2[STARTT / 2]));
        (void)dead;
    }

    __shared__ __align__(16) float part[2][T];

    const float* fb = feats + (size_t)b * S * T;
    float* hb = g_hist + (size_t)b * S * T;

    float p0 = fb[j] + cstart;
    part[0][j] = p0;
    hb[j] = p0;
    float e1 = fb[T + j];
    float e2 = fb[2 * T + j];
    __syncthreads();

    const unsigned sbase0 = (unsigned)__cvta_generic_to_shared(&part[0][0]);

#pragma unroll 1
    for (int s = 1; s < S; s++) {
        float ecur = e1;
        e1 = e2;
        if (s + 2 < S) e2 = fb[(s + 2) * T + j];

        const unsigned pbase =
            sbase0 + (((s - 1) & 1) ? (unsigned)(T * 4) : 0u);

        float m0, m1, m2, m3;
        asm volatile(
            "{\n\t"
            ".reg .b64 p0, p1, s0, s1;\n\t"
            "ld.shared.v2.b64 {p0, p1}, [%4];\n\t"
            "add.rn.f32x2 s0, p0, %5;\n\t"
            "add.rn.f32x2 s1, p1, %6;\n\t"
            "mov.b64 {%0, %1}, s0;\n\t"
            "mov.b64 {%2, %3}, s1;\n\t"
            "}"
            : "=f"(m0), "=f"(m1), "=f"(m2), "=f"(m3)
            : "r"(pbase), "l"(c2[0]), "l"(c2[1]));
#pragma unroll
        for (int q = 1; q < 32; q++) {
            asm volatile(
                "{\n\t"
                ".reg .b64 p0, p1, s0, s1;\n\t"
                ".reg .f32 a0, a1, a2, a3;\n\t"
                "ld.shared.v2.b64 {p0, p1}, [%4];\n\t"
                "add.rn.f32x2 s0, p0, %5;\n\t"
                "add.rn.f32x2 s1, p1, %6;\n\t"
                "mov.b64 {a0, a1}, s0;\n\t"
                "mov.b64 {a2, a3}, s1;\n\t"
                "max.f32 %0, %0, a0;\n\t"
                "max.f32 %1, %1, a1;\n\t"
                "max.f32 %2, %2, a2;\n\t"
                "max.f32 %3, %3, a3;\n\t"
                "}"
                : "+f"(m0), "+f"(m1), "+f"(m2), "+f"(m3)
                : "r"(pbase + 16u * q), "l"(c2[2 * q]), "l"(c2[2 * q + 1]));
        }
        float np = fmaxf(fmaxf(m0, m1), fmaxf(m2, m3)) + ecur;
        part[s & 1][j] = np;
        hb[s * T + j] = np;
        __syncthreads();
    }
}

// monotonic float -> u32 key (order preserving for finite floats)
__device__ __forceinline__ unsigned fkey(float f) {
    unsigned u = __float_as_uint(f);
    return u ^ ((unsigned)((int)u >> 31) | 0x80000000u);
}

// first-index argmax over the warp's 4-per-lane keys; returns index to all
__device__ __forceinline__ int warp_argmax4(unsigned k0, unsigned k1,
                                            unsigned k2, unsigned k3, int l) {
    unsigned ka = (k0 > k1) ? k0 : k1;
    unsigned kb = (k2 > k3) ? k2 : k3;
    unsigned lm = (ka > kb) ? ka : kb;
    unsigned g = __reduce_max_sync(0xffffffffu, lm);
    unsigned bm = (k0 == g ? 1u : 0u) | (k1 == g ? 2u : 0u) |
                  (k2 == g ? 4u : 0u) | (k3 == g ? 8u : 0u);
    unsigned idxc = bm ? (unsigned)(4 * l + (__ffs((int)bm) - 1))
                       : 0x40000000u;
    return (int)__reduce_min_sync(0xffffffffu, idxc);
}

// ---------------------------------------------------------------------------
// Kernel 2: per-WARP traceback. Grid 64 x 128 threads; warp w of block g
// traces batch 4g+w. hist/feats rows streamed through a 4-slot smem ring
// filled with cp.async + per-group commit/wait_prior(3) -> the consumer
// waits ONLY for the 4-iteration-old group (no scoreboard aliasing with the
// just-issued prefetch, unlike an LDG register ring).
// ---------------------------------------------------------------------------
__global__ __launch_bounds__(128, 1) void k_traceback(
    const float* __restrict__ feats, const float* __restrict__ trans,
    const void* __restrict__ mask, float* __restrict__ out) {
    const int tid = threadIdx.x;
    const int wid = tid >> 5;
    const int l = tid & 31;
    const int b = blockIdx.x * 4 + wid;

    extern __shared__ float smem[];
    float* sT = smem;                       // [T][TB_PITCH]
    float* wring = smem + T * TB_PITCH + wid * 1024;  // 4 slots x 256 floats

    // cooperative transpose of trans into padded smem (one-time)
    for (int k = tid; k < T * T; k += 128) {
        int i = k >> 7;
        int jj = k & 127;
        sT[jj * TB_PITCH + i] = trans[k];
    }
    __syncthreads();

    // ---- per-warp length: lane l counts 16 consecutive mask entries ----
    const unsigned w0 = *(const unsigned*)mask;  // dtype signature
    int cnt = 0;
    if (w0 == 0x01010101u) {  // 1-byte bool
        const uint4* m16 = (const uint4*)((const unsigned char*)mask +
                                          (size_t)b * S + l * 16);
        uint4 v = *m16;
        cnt = __popc(v.x) + __popc(v.y) + __popc(v.z) + __popc(v.w);
    } else if (w0 == 0x3F800000u) {  // float32
        const float* mf = (const float*)mask + (size_t)b * S + l * 16;
#pragma unroll
        for (int t = 0; t < 16; t++) cnt += (mf[t] != 0.f);
    } else if (w0 == 0x3F803F80u || w0 == 0x3C003C00u) {  // bf16 / f16
        const unsigned short* mh =
            (const unsigned short*)mask + (size_t)b * S + l * 16;
#pragma unroll
        for (int t = 0; t < 16; t++) cnt += (mh[t] != 0);
    } else {  // int32 0/1
        const int* mi = (const int*)mask + (size_t)b * S + l * 16;
#pragma unroll
        for (int t = 0; t < 16; t++) cnt += (mi[t] != 0);
    }
    cnt = __reduce_add_sync(0xffffffffu, cnt);
    const int last_pos = cnt - 1;

    const float* hist_b = g_hist + (size_t)b * S * T;
    const float* feats_b = feats + (size_t)b * S * T;

    // ---- final pointer: argmax_i(hist[last_pos][i] + trans[i][STOP]) ----
    int pointer;
    {
        float4 h = reinterpret_cast<const float4*>(hist_b +
                                                   last_pos * T)[l];
        float4 tr = reinterpret_cast<const float4*>(sT + STOPT * TB_PITCH)[l];
        unsigned k0 = fkey(h.x + tr.x), k1 = fkey(h.y + tr.y);
        unsigned k2 = fkey(h.z + tr.z), k3 = fkey(h.w + tr.w);
        pointer = warp_argmax4(k0, k1, k2, k3, l);
    }

    float* ob = out + (size_t)b * S;

    // positions past the sequence: zeros (matches zeroed back_points rows)
    for (int s = last_pos + 1 + l; s < S - 1; s += 32) ob[s] = 0.0f;
    if (l == 0) {
        ob[S - 1] = (float)pointer;
        ob[last_pos] = (float)pointer;
    }

    int ptr = pointer;
    const int s0 = last_pos - 1;
    if (s0 < 0) return;

    // ---- prologue: fill 4 ring slots (steps s0 .. s0-3) ----
#pragma unroll
    for (int k = 0; k < 4; k++) {
        int sp = s0 - k;
        if (sp < 0) sp = 0;
        __pipeline_memcpy_async(wring + k * 256 + 4 * l,
                                hist_b + sp * T + 4 * l, 16);
        __pipeline_memcpy_async(wring + k * 256 + 128 + 4 * l,
                                feats_b + (sp + 1) * T + 4 * l, 16);
        __pipeline_commit();
    }

    int slot = 0;
    for (int s = s0; s >= 0; --s) {
        // wait only for the oldest outstanding group (this slot's data)
        __pipeline_wait_prior(3);
        float4 h = *reinterpret_cast<const float4*>(wring + slot * 256 + 4 * l);
        float4 er =
            *reinterpret_cast<const float4*>(wring + slot * 256 + 128 + 4 * l);

        // refill this slot for step s-4 (ptr-independent addresses)
        int sp = s - 4;
        if (sp < 0) sp = 0;
        __pipeline_memcpy_async(wring + slot * 256 + 4 * l,
                                hist_b + sp * T + 4 * l, 16);
        __pipeline_memcpy_async(wring + slot * 256 + 128 + 4 * l,
                                feats_b + (sp + 1) * T + 4 * l, 16);
        __pipeline_commit();

        // trans[:, ptr] chunk from padded smem (LDS.128, conflict-free)
        float4 tc = reinterpret_cast<const float4*>(sT + ptr * TB_PITCH)[l];

        // scalar e = feats[b][s+1][ptr] extracted from prefetched row
        int comp = ptr & 3, src = ptr >> 2;
        float cand = (comp == 0) ? er.x
                   : (comp == 1) ? er.y
                   : (comp == 2) ? er.z : er.w;
        float e = __shfl_sync(0xffffffffu, cand, src);

        // exact replication of reference: (part + trans) + e, argmax first-idx
        unsigned k0 = fkey((h.x + tc.x) + e);
        unsigned k1 = fkey((h.y + tc.y) + e);
        unsigned k2 = fkey((h.z + tc.z) + e);
        unsigned k3 = fkey((h.w + tc.w) + e);
        ptr = warp_argmax4(k0, k1, k2, k3, l);
        if (l == 0) ob[s] = (float)ptr;

        slot = (slot + 1) & 3;
    }
}

// ---------------------------------------------------------------------------
extern "C" void kernel_launch(void* const* d_in, const int* in_sizes, int n_in,
                              void* d_out, int out_size) {
    // Identify inputs by element count:
    //   feats 16777216, transitions 16384, mask 131072
    const float* feats = nullptr;
    const void* mask = nullptr;
    const float* trans = nullptr;
    for (int i = 0; i < n_in; i++) {
        int n = in_sizes[i];
        if (n == B * S * T) feats = (const float*)d_in[i];
        else if (n == T * T) trans = (const float*)d_in[i];
        else mask = d_in[i];
    }
    float* out = (float*)d_out;
    (void)out_size;

    // smem: transT (67584 B) + 4 warps x 4 slots x 256 floats (16384 B)
    const int smem_tb = T * TB_PITCH * sizeof(float) + 4 * 4 * 256 * 4;
    cudaFuncSetAttribute(k_traceback,
                         cudaFuncAttributeMaxDynamicSharedMemorySize, smem_tb);

    k_forward<<<B, T>>>(feats, trans);
    k_traceback<<<B / 4, T, smem_tb>>>(feats, trans, mask, out);
}

// round 9
// speedup vs baseline: 1.7160x; 1.0587x over previous
#include <cuda_runtime.h>
#include <cuda_pipeline_primitives.h>

#define B 256
#define S 512
#define T 128
#define STARTT 125
#define STOPT 126
#define TB_PITCH 132  // padded row pitch (floats) for smem transT

// 64MB part-history scratch: hist[b][s][t]
__device__ float g_hist[(size_t)B * S * T];

// ---------------------------------------------------------------------------
// Kernel 1: forward Viterbi max-plus recurrence. One block per batch.
// Thread j holds trans[:, j] in 128 scalar registers. Scalar inner loop:
// per 4 "from" states: 1 LDS.128 + 4 FADD + 4 FMNMX (~288 issues/warp/step;
// the f32x2 packed variant measured WORSE due to un-elided b64 unpack MOVs).
// ---------------------------------------------------------------------------
__global__ __launch_bounds__(128, 2) void k_forward(
    const float* __restrict__ feats, const float* __restrict__ trans) {
    const int b = blockIdx.x;
    const int j = threadIdx.x;

    // trans column j into registers (coalesced per i across threads)
    float c[T];
#pragma unroll
    for (int i = 0; i < T; i++) c[i] = trans[i * T + j];

    __shared__ __align__(16) float part[2][T];

    const float* fb = feats + (size_t)b * S * T;
    float* hb = g_hist + (size_t)b * S * T;

    // s = 0: part0 = emit[0] + trans[START][:]
    float p0 = fb[j] + c[STARTT];
    part[0][j] = p0;
    hb[j] = p0;
    // emission prefetch, 2 deep
    float e1 = fb[T + j];
    float e2 = fb[2 * T + j];
    __syncthreads();

#pragma unroll 1
    for (int s = 1; s < S; s++) {
        float ecur = e1;
        e1 = e2;
        if (s + 2 < S) e2 = fb[(s + 2) * T + j];

        const float4* pp = reinterpret_cast<const float4*>(part[(s - 1) & 1]);
        float4 v0 = pp[0];
        float m0 = v0.x + c[0];
        float m1 = v0.y + c[1];
        float m2 = v0.z + c[2];
        float m3 = v0.w + c[3];
#pragma unroll
        for (int q = 1; q < 32; q++) {
            float4 u = pp[q];
            m0 = fmaxf(m0, u.x + c[4 * q + 0]);
            m1 = fmaxf(m1, u.y + c[4 * q + 1]);
            m2 = fmaxf(m2, u.z + c[4 * q + 2]);
            m3 = fmaxf(m3, u.w + c[4 * q + 3]);
        }
        float np = fmaxf(fmaxf(m0, m1), fmaxf(m2, m3)) + ecur;
        part[s & 1][j] = np;
        hb[s * T + j] = np;
        __syncthreads();
    }
}

// monotonic float -> u32 key (order preserving for finite floats)
__device__ __forceinline__ unsigned fkey(float f) {
    unsigned u = __float_as_uint(f);
    return u ^ ((unsigned)((int)u >> 31) | 0x80000000u);
}

// first-index argmax over the warp's 4-per-lane keys; returns index to all
__device__ __forceinline__ int warp_argmax4(unsigned k0, unsigned k1,
                                            unsigned k2, unsigned k3, int l) {
    unsigned ka = (k0 > k1) ? k0 : k1;
    unsigned kb = (k2 > k3) ? k2 : k3;
    unsigned lm = (ka > kb) ? ka : kb;
    unsigned g = __reduce_max_sync(0xffffffffu, lm);
    unsigned bm = (k0 == g ? 1u : 0u) | (k1 == g ? 2u : 0u) |
                  (k2 == g ? 4u : 0u) | (k3 == g ? 8u : 0u);
    unsigned idxc = bm ? (unsigned)(4 * l + (__ffs((int)bm) - 1))
                       : 0x40000000u;
    return (int)__reduce_min_sync(0xffffffffu, idxc);
}

// ---------------------------------------------------------------------------
// Kernel 2: per-WARP traceback. Grid 64 x 128 threads; warp w of block g
// traces batch 4g+w. hist/feats rows streamed through a 4-slot smem ring
// (cp.async + per-group commit/wait_prior(3)). The emission scalar e is read
// directly from the smem ring at uniform address [ptr] (broadcast LDS),
// removing the shfl+select from the serial chain.
// ---------------------------------------------------------------------------
__global__ __launch_bounds__(128, 1) void k_traceback(
    const float* __restrict__ feats, const float* __restrict__ trans,
    const void* __restrict__ mask, float* __restrict__ out) {
    const int tid = threadIdx.x;
    const int wid = tid >> 5;
    const int l = tid & 31;
    const int b = blockIdx.x * 4 + wid;

    extern __shared__ float smem[];
    float* sT = smem;                                  // [T][TB_PITCH]
    float* wring = smem + T * TB_PITCH + wid * 1024;   // 4 slots x 256 floats

    // cooperative transpose of trans into padded smem (one-time)
    for (int k = tid; k < T * T; k += 128) {
        int i = k >> 7;
        int jj = k & 127;
        sT[jj * TB_PITCH + i] = trans[k];
    }
    __syncthreads();

    // ---- per-warp length: lane l counts 16 consecutive mask entries ----
    const unsigned w0 = *(const unsigned*)mask;  // dtype signature
    int cnt = 0;
    if (w0 == 0x01010101u) {  // 1-byte bool
        const uint4* m16 = (const uint4*)((const unsigned char*)mask +
                                          (size_t)b * S + l * 16);
        uint4 v = *m16;
        cnt = __popc(v.x) + __popc(v.y) + __popc(v.z) + __popc(v.w);
    } else if (w0 == 0x3F800000u) {  // float32
        const float* mf = (const float*)mask + (size_t)b * S + l * 16;
#pragma unroll
        for (int t = 0; t < 16; t++) cnt += (mf[t] != 0.f);
    } else if (w0 == 0x3F803F80u || w0 == 0x3C003C00u) {  // bf16 / f16
        const unsigned short* mh =
            (const unsigned short*)mask + (size_t)b * S + l * 16;
#pragma unroll
        for (int t = 0; t < 16; t++) cnt += (mh[t] != 0);
    } else {  // int32 0/1
        const int* mi = (const int*)mask + (size_t)b * S + l * 16;
#pragma unroll
        for (int t = 0; t < 16; t++) cnt += (mi[t] != 0);
    }
    cnt = __reduce_add_sync(0xffffffffu, cnt);
    const int last_pos = cnt - 1;

    const float* hist_b = g_hist + (size_t)b * S * T;
    const float* feats_b = feats + (size_t)b * S * T;

    // ---- final pointer: argmax_i(hist[last_pos][i] + trans[i][STOP]) ----
    int pointer;
    {
        float4 h = reinterpret_cast<const float4*>(hist_b + last_pos * T)[l];
        float4 tr = reinterpret_cast<const float4*>(sT + STOPT * TB_PITCH)[l];
        unsigned k0 = fkey(h.x + tr.x), k1 = fkey(h.y + tr.y);
        unsigned k2 = fkey(h.z + tr.z), k3 = fkey(h.w + tr.w);
        pointer = warp_argmax4(k0, k1, k2, k3, l);
    }

    float* ob = out + (size_t)b * S;

    // positions past the sequence: zeros (matches zeroed back_points rows)
    for (int s = last_pos + 1 + l; s < S - 1; s += 32) ob[s] = 0.0f;
    if (l == 0) {
        ob[S - 1] = (float)pointer;
        ob[last_pos] = (float)pointer;
    }

    int ptr = pointer;
    const int s0 = last_pos - 1;
    if (s0 < 0) return;

    // ---- prologue: fill 4 ring slots (steps s0 .. s0-3) ----
#pragma unroll
    for (int k = 0; k < 4; k++) {
        int sp = s0 - k;
        if (sp < 0) sp = 0;
        __pipeline_memcpy_async(wring + k * 256 + 4 * l,
                                hist_b + sp * T + 4 * l, 16);
        __pipeline_memcpy_async(wring + k * 256 + 128 + 4 * l,
                                feats_b + (sp + 1) * T + 4 * l, 16);
        __pipeline_commit();
    }

    int slot = 0;
    for (int s = s0; s >= 0; --s) {
        // wait only for the oldest outstanding group (this slot's data)
        __pipeline_wait_prior(3);
        float4 h = *reinterpret_cast<const float4*>(wring + slot * 256 + 4 * l);
        // scalar e = feats[b][s+1][ptr]: uniform-address broadcast LDS
        float e = wring[slot * 256 + 128 + ptr];

        // refill this slot for step s-4 (ptr-independent addresses)
        int sp = s - 4;
        if (sp < 0) sp = 0;
        __pipeline_memcpy_async(wring + slot * 256 + 4 * l,
                                hist_b + sp * T + 4 * l, 16);
        __pipeline_memcpy_async(wring + slot * 256 + 128 + 4 * l,
                                feats_b + (sp + 1) * T + 4 * l, 16);
        __pipeline_commit();

        // trans[:, ptr] chunk from padded smem (LDS.128, conflict-free)
        float4 tc = reinterpret_cast<const float4*>(sT + ptr * TB_PITCH)[l];

        // exact replication of reference: (part + trans) + e, argmax first-idx
        unsigned k0 = fkey((h.x + tc.x) + e);
        unsigned k1 = fkey((h.y + tc.y) + e);
        unsigned k2 = fkey((h.z + tc.z) + e);
        unsigned k3 = fkey((h.w + tc.w) + e);
        ptr = warp_argmax4(k0, k1, k2, k3, l);
        if (l == 0) ob[s] = (float)ptr;

        slot = (slot + 1) & 3;
    }
}

// ---------------------------------------------------------------------------
extern "C" void kernel_launch(void* const* d_in, const int* in_sizes, int n_in,
                              void* d_out, int out_size) {
    // Identify inputs by element count:
    //   feats 16777216, transitions 16384, mask 131072
    const float* feats = nullptr;
    const void* mask = nullptr;
    const float* trans = nullptr;
    for (int i = 0; i < n_in; i++) {
        int n = in_sizes[i];
        if (n == B * S * T) feats = (const float*)d_in[i];
        else if (n == T * T) trans = (const float*)d_in[i];
        else mask = d_in[i];
    }
    float* out = (float*)d_out;
    (void)out_size;

    // smem: transT (67584 B) + 4 warps x 4 slots x 256 floats (16384 B)
    const int smem_tb = T * TB_PITCH * sizeof(float) + 4 * 4 * 256 * 4;
    cudaFuncSetAttribute(k_traceback,
                         cudaFuncAttributeMaxDynamicSharedMemorySize, smem_tb);

    k_forward<<<B, T>>>(feats, trans);
    k_traceback<<<B / 4, T, smem_tb>>>(feats, trans, mask, out);
}